// round 13
// baseline (speedup 1.0000x reference)
#include <cuda_runtime.h>

// G2InvariantAttention — GB300 sm_103a — Round 13: two queries per thread.
//   * Each thread processes queries n and n+256 of a 512-query block: every
//     ld.shared key-pair now feeds 30 FMA2 (2 queries) instead of 15 —
//     halves LDS slots per FMA and doubles per-warp ILP (2 indep chains).
//   * regs ~82, __launch_bounds__(256,3) (cap 85) -> occ 3, 6 warps/SMSP
//     with 2x ILP each (effective 12 chains vs R8's 8).
//   * grid (4, 32, 8) = 1024 CTAs; smem 8KB; loop body math identical.
//   * combine = R12 PDL version (TPB=64, front-loaded q, 6.5us) — unchanged.
// Exact math: oct_cross(k,k)=0, v==k, scale folded into q, no max-subtraction
// (logits bounded), linear partial combination via REDG into 2MB acc.

#define N_TOK   2048
#define N_HEAD  16
#define N_BATCH 2
#define DMODEL  128
#define TPB     256
#define CTPB    64
#define KSPLIT  8
#define KCHUNK  (N_TOK / KSPLIT)      // 256 keys per CTA
#define NPAIR   (KCHUNK / 2)          // 128 key pairs
#define QBLK    512                   // queries per CTA (2 per thread)

typedef unsigned long long u64;

// Per-query accumulator: [B*H*N][8 floats] = 2 MB. Zero-init at module load;
// the combine kernel re-zeros after reading -> deterministic across replays.
__device__ float g_acc[(size_t)N_BATCH * N_HEAD * N_TOK * 8];

__device__ __forceinline__ u64 f2pack(float lo, float hi) {
    u64 r; asm("mov.b64 %0,{%1,%2};" : "=l"(r) : "f"(lo), "f"(hi)); return r;
}
__device__ __forceinline__ void f2unpack(u64 v, float& lo, float& hi) {
    asm("mov.b64 {%0,%1},%2;" : "=f"(lo), "=f"(hi) : "l"(v));
}
__device__ __forceinline__ u64 f2fma(u64 a, u64 b, u64 c) {
    u64 d; asm("fma.rn.f32x2 %0,%1,%2,%3;" : "=l"(d) : "l"(a), "l"(b), "l"(c)); return d;
}
__device__ __forceinline__ u64 f2mul(u64 a, u64 b) {
    u64 d; asm("mul.rn.f32x2 %0,%1,%2;" : "=l"(d) : "l"(a), "l"(b)); return d;
}
__device__ __forceinline__ u64 f2add(u64 a, u64 b) {
    u64 d; asm("add.rn.f32x2 %0,%1,%2;" : "=l"(d) : "l"(a), "l"(b)); return d;
}
__device__ __forceinline__ float fast_ex2(float x) {
    float r; asm("ex2.approx.f32 %0,%1;" : "=f"(r) : "f"(x)); return r;
}

// ---------------- Kernel 1: partial, 2 queries/thread over a 256-key slice --
__global__ void __launch_bounds__(TPB, 3) g2_attn_partial(
    const float* __restrict__ o, const float* __restrict__ mix)
{
    // Pair-major layout: sP[pair][dim][parity], dims 0..6, slot 7 = pad.
    __shared__ float sP[NPAIR * 16];   // 8 KB

    const int bh  = blockIdx.y;
    const int h   = bh & (N_HEAD - 1);
    const int b   = bh >> 4;
    const int ks  = blockIdx.z;
    const int tid = threadIdx.x;
    const float* obase = o + ((size_t)b * N_TOK) * DMODEL + h * 8;

    // Each thread loads one key of this CTA's slice, scatters into pair layout.
    {
        int j  = tid;                       // 0..255 == KCHUNK
        int jg = ks * KCHUNK + j;
        float4 v0 = *(const float4*)(obase + (size_t)jg * DMODEL);      // real,i0,i1,i2
        float4 v1 = *(const float4*)(obase + (size_t)jg * DMODEL + 4);  // i3..i6
        float* dst = sP + (j >> 1) * 16 + (j & 1);
        dst[0]  = v0.y;  dst[2]  = v0.z;  dst[4]  = v0.w;  dst[6]  = v1.x;
        dst[8]  = v1.y;  dst[10] = v1.z;  dst[12] = v1.w;  dst[14] = 0.0f;  // pad
    }
    __syncthreads();

    const int nA = blockIdx.x * QBLK + tid;        // query A
    const int nB = nA + TPB;                       // query B

    // w_k = sigmoid(m0-m1); fold w_k * log2e / sqrt(7) into q.
    float m0 = mix[2 * h], m1 = mix[2 * h + 1];
    float wk = 1.0f / (1.0f + __expf(m1 - m0));
    const float coef = wk * 1.4426950408889634f * 0.3779644730092272f;

    float4 qa0 = *(const float4*)(obase + (size_t)nA * DMODEL);
    float4 qa1 = *(const float4*)(obase + (size_t)nA * DMODEL + 4);
    float4 qb0 = *(const float4*)(obase + (size_t)nB * DMODEL);
    float4 qb1 = *(const float4*)(obase + (size_t)nB * DMODEL + 4);

    u64 qA0 = f2pack(qa0.y * coef, qa0.y * coef);
    u64 qA1 = f2pack(qa0.z * coef, qa0.z * coef);
    u64 qA2 = f2pack(qa0.w * coef, qa0.w * coef);
    u64 qA3 = f2pack(qa1.x * coef, qa1.x * coef);
    u64 qA4 = f2pack(qa1.y * coef, qa1.y * coef);
    u64 qA5 = f2pack(qa1.z * coef, qa1.z * coef);
    u64 qA6 = f2pack(qa1.w * coef, qa1.w * coef);
    u64 qB0 = f2pack(qb0.y * coef, qb0.y * coef);
    u64 qB1 = f2pack(qb0.z * coef, qb0.z * coef);
    u64 qB2 = f2pack(qb0.w * coef, qb0.w * coef);
    u64 qB3 = f2pack(qb1.x * coef, qb1.x * coef);
    u64 qB4 = f2pack(qb1.y * coef, qb1.y * coef);
    u64 qB5 = f2pack(qb1.z * coef, qb1.z * coef);
    u64 qB6 = f2pack(qb1.w * coef, qb1.w * coef);

    u64 aA0 = 0, aA1 = 0, aA2 = 0, aA3 = 0, aA4 = 0, aA5 = 0, aA6 = 0, lA = 0;
    u64 aB0 = 0, aB1 = 0, aB2 = 0, aB3 = 0, aB4 = 0, aB5 = 0, aB6 = 0, lB = 0;

    unsigned sbase;
    asm("{ .reg .u64 t; cvta.to.shared.u64 t, %1; cvt.u32.u64 %0, t; }"
        : "=r"(sbase) : "l"(sP));

    unsigned addr = sbase;
    for (int p = 0; p < NPAIR; p++, addr += 64) {
        u64 P0, P1, P2, P3, P4, P5, P6;
        asm("ld.shared.v2.b64 {%0,%1},[%2];"    : "=l"(P0), "=l"(P1) : "r"(addr));
        asm("ld.shared.v2.b64 {%0,%1},[%2+16];" : "=l"(P2), "=l"(P3) : "r"(addr));
        asm("ld.shared.v2.b64 {%0,%1},[%2+32];" : "=l"(P4), "=l"(P5) : "r"(addr));
        asm("ld.shared.b64 %0,[%1+48];"         : "=l"(P6)           : "r"(addr));

        // Two independent score chains (queries A and B share the K regs).
        u64 sA = f2mul(qA0, P0);
        u64 sB = f2mul(qB0, P0);
        sA = f2fma(qA1, P1, sA);  sB = f2fma(qB1, P1, sB);
        sA = f2fma(qA2, P2, sA);  sB = f2fma(qB2, P2, sB);
        sA = f2fma(qA3, P3, sA);  sB = f2fma(qB3, P3, sB);
        sA = f2fma(qA4, P4, sA);  sB = f2fma(qB4, P4, sB);
        sA = f2fma(qA5, P5, sA);  sB = f2fma(qB5, P5, sB);
        sA = f2fma(qA6, P6, sA);  sB = f2fma(qB6, P6, sB);

        float xa, xb, ya, yb;
        f2unpack(sA, xa, xb);
        f2unpack(sB, ya, yb);
        u64 eA = f2pack(fast_ex2(xa), fast_ex2(xb));
        u64 eB = f2pack(fast_ex2(ya), fast_ex2(yb));

        aA0 = f2fma(P0, eA, aA0);  aB0 = f2fma(P0, eB, aB0);
        aA1 = f2fma(P1, eA, aA1);  aB1 = f2fma(P1, eB, aB1);
        aA2 = f2fma(P2, eA, aA2);  aB2 = f2fma(P2, eB, aB2);
        aA3 = f2fma(P3, eA, aA3);  aB3 = f2fma(P3, eB, aB3);
        aA4 = f2fma(P4, eA, aA4);  aB4 = f2fma(P4, eB, aB4);
        aA5 = f2fma(P5, eA, aA5);  aB5 = f2fma(P5, eB, aB5);
        aA6 = f2fma(P6, eA, aA6);  aB6 = f2fma(P6, eB, aB6);
        lA  = f2add(lA, eA);       lB  = f2add(lB, eB);
    }

    // Horizontal sums + RED for both queries.
    {
        float lo, hi, y[8];
        f2unpack(aA0, lo, hi); y[0] = lo + hi;
        f2unpack(aA1, lo, hi); y[1] = lo + hi;
        f2unpack(aA2, lo, hi); y[2] = lo + hi;
        f2unpack(aA3, lo, hi); y[3] = lo + hi;
        f2unpack(aA4, lo, hi); y[4] = lo + hi;
        f2unpack(aA5, lo, hi); y[5] = lo + hi;
        f2unpack(aA6, lo, hi); y[6] = lo + hi;
        f2unpack(lA,  lo, hi); y[7] = lo + hi;
        float* acc = g_acc + (((size_t)bh * N_TOK + nA) << 3);
        #pragma unroll
        for (int i = 0; i < 8; i++) atomicAdd(acc + i, y[i]);
    }
    {
        float lo, hi, y[8];
        f2unpack(aB0, lo, hi); y[0] = lo + hi;
        f2unpack(aB1, lo, hi); y[1] = lo + hi;
        f2unpack(aB2, lo, hi); y[2] = lo + hi;
        f2unpack(aB3, lo, hi); y[3] = lo + hi;
        f2unpack(aB4, lo, hi); y[4] = lo + hi;
        f2unpack(aB5, lo, hi); y[5] = lo + hi;
        f2unpack(aB6, lo, hi); y[6] = lo + hi;
        f2unpack(lB,  lo, hi); y[7] = lo + hi;
        float* acc = g_acc + (((size_t)bh * N_TOK + nB) << 3);
        #pragma unroll
        for (int i = 0; i < 8; i++) atomicAdd(acc + i, y[i]);
    }
}

// ---------------- Kernel 2: PDL epilogue (loads q early, syncs, reads acc) --
__global__ void __launch_bounds__(CTPB) g2_attn_combine(
    const float* __restrict__ o,
    const float* __restrict__ alpha, const float* __restrict__ beta,
    float* __restrict__ out)
{
    const int qi = blockIdx.x * CTPB + threadIdx.x;  // 0 .. B*H*N-1
    const int bh = qi >> 11;
    const int n  = qi & (N_TOK - 1);
    const int h  = bh & (N_HEAD - 1);
    const int b  = bh >> 4;

    // ---- Independent of the partial: issue these loads BEFORE the sync.
    const float* obase = o + ((size_t)b * N_TOK) * DMODEL + h * 8;
    float4 q0 = *(const float4*)(obase + (size_t)n * DMODEL);
    float4 q1 = *(const float4*)(obase + (size_t)n * DMODEL + 4);
    float av = 1.0f / (1.0f + __expf(-alpha[h]));
    float bv = tanhf(beta[h]);

    // ---- Wait for the partial grid to complete (PDL).
    cudaGridDependencySynchronize();

    float* acc = g_acc + ((size_t)qi << 3);
    float4 w0 = *(const float4*)(acc);
    float4 w1 = *(const float4*)(acc + 4);
    float y[7] = {w0.x, w0.y, w0.z, w0.w, w1.x, w1.y, w1.z};
    float l = w1.w;

    // Restore zeros for the next graph replay (deterministic state).
    *(float4*)(acc)     = make_float4(0.f, 0.f, 0.f, 0.f);
    *(float4*)(acc + 4) = make_float4(0.f, 0.f, 0.f, 0.f);

    float rinv = 1.0f / l;
    #pragma unroll
    for (int i = 0; i < 7; i++) y[i] *= rinv;

    float real = q0.x;
    float qo[7] = {q0.y, q0.z, q0.w, q1.x, q1.y, q1.z, q1.w};

    // Octonion cross product c = qo x y.
    float c[7];
    #pragma unroll
    for (int i = 0; i < 7; i++) c[i] = 0.0f;
    const int FI[7] = {0, 0, 0, 1, 1, 2, 2};
    const int FJ[7] = {1, 3, 6, 3, 4, 3, 5};
    const int FK[7] = {2, 4, 5, 5, 6, 6, 4};
    #pragma unroll
    for (int t = 0; t < 7; t++) {
        int i = FI[t], j = FJ[t], k = FK[t];
        c[k] += qo[i] * y[j] - qo[j] * y[i];
        c[i] += qo[j] * y[k] - qo[k] * y[j];
        c[j] += qo[k] * y[i] - qo[i] * y[k];
    }

    float im[7];
    float ns = real * real;
    #pragma unroll
    for (int i = 0; i < 7; i++) {
        im[i] = av * y[i] + bv * c[i];
        ns += im[i] * im[i];
    }
    float inv = 1.0f / fmaxf(sqrtf(ns), 1e-12f);

    float* op = out + ((size_t)(b * N_TOK + n)) * DMODEL + h * 8;
    *(float4*)(op)     = make_float4(real * inv, im[0] * inv, im[1] * inv, im[2] * inv);
    *(float4*)(op + 4) = make_float4(im[3] * inv, im[4] * inv, im[5] * inv, im[6] * inv);
}

extern "C" void kernel_launch(void* const* d_in, const int* in_sizes, int n_in,
                              void* d_out, int out_size) {
    const float* o     = (const float*)d_in[0];
    const float* mix   = (const float*)d_in[1];
    const float* alpha = (const float*)d_in[2];
    const float* beta  = (const float*)d_in[3];
    float* out = (float*)d_out;
    (void)in_sizes; (void)n_in; (void)out_size;

    dim3 grid1(N_TOK / QBLK, N_BATCH * N_HEAD, KSPLIT);   // (4, 32, 8) = 1024 CTAs
    g2_attn_partial<<<grid1, TPB>>>(o, mix);

    // Combine with Programmatic Dependent Launch.
    cudaLaunchConfig_t cfg = {};
    cfg.gridDim  = dim3(N_BATCH * N_HEAD * N_TOK / CTPB, 1, 1);   // 1024 CTAs
    cfg.blockDim = dim3(CTPB, 1, 1);
    cudaLaunchAttribute attrs[1];
    attrs[0].id = cudaLaunchAttributeProgrammaticStreamSerialization;
    attrs[0].val.programmaticStreamSerializationAllowed = 1;
    cfg.attrs = attrs;
    cfg.numAttrs = 1;
    cudaLaunchKernelEx(&cfg, g2_attn_combine, o, alpha, beta, out);
}

// round 14
// speedup vs baseline: 1.0211x; 1.0211x over previous
#include <cuda_runtime.h>

// G2InvariantAttention — GB300 sm_103a — Round 14: tensor-core scores.
//   S = Q·K^T is a GEMM with K-dim 8 (7 imag dims + zero pad) -> exactly one
//   mma.sync.m16n8k8.tf32 k-step. Per warp the Q A-fragment is loaded ONCE
//   and reused for all 2048 keys. exp on the C fragment in registers; the
//   attention-weighted sum stays SIMT fp32 (4 FMA2/qk, was 7.5 with scores).
//   One CTA per (bh, 128 queries) = 512 CTAs = one wave. No split-K, no
//   scratch, no atomics, no second kernel: epilogue fused (quad shuffle
//   reduce; lane%4==0 finalizes 2 rows).
//   tf32 only touches the logits: err ~1e-3 on logits -> ~1e-4 on outputs.
// Exact math: oct_cross(k,k)=0, v==k, scale wk*log2e/sqrt(7) folded into Q,
// no max-subtraction (logits bounded), K plane slot7=1.0 -> denominator free.

#define N_TOK   2048
#define N_HEAD  16
#define N_BATCH 2
#define DMODEL  128
#define TPB     256
#define CHUNK   256                  // keys per smem chunk (== TPB)
#define NKB     (CHUNK / 8)          // 32 mma steps per chunk
#define NCHUNK  (N_TOK / CHUNK)      // 8
#define QT      128                  // queries per CTA

typedef unsigned long long u64;

__device__ __forceinline__ u64 f2pack(float lo, float hi) {
    u64 r; asm("mov.b64 %0,{%1,%2};" : "=l"(r) : "f"(lo), "f"(hi)); return r;
}
__device__ __forceinline__ void f2unpack(u64 v, float& lo, float& hi) {
    asm("mov.b64 {%0,%1},%2;" : "=f"(lo), "=f"(hi) : "l"(v));
}
__device__ __forceinline__ u64 f2fma(u64 a, u64 b, u64 c) {
    u64 d; asm("fma.rn.f32x2 %0,%1,%2,%3;" : "=l"(d) : "l"(a), "l"(b), "l"(c)); return d;
}
__device__ __forceinline__ u64 f2add(u64 a, u64 b) {
    u64 d; asm("add.rn.f32x2 %0,%1,%2;" : "=l"(d) : "l"(a), "l"(b)); return d;
}
__device__ __forceinline__ float fast_ex2(float x) {
    float r; asm("ex2.approx.f32 %0,%1;" : "=f"(r) : "f"(x)); return r;
}
__device__ __forceinline__ unsigned tf32cvt(float x) {
    unsigned r; asm("cvt.rna.tf32.f32 %0,%1;" : "=r"(r) : "f"(x)); return r;
}

__global__ void __launch_bounds__(TPB, 4) g2_attn_tc(
    const float* __restrict__ o, const float* __restrict__ mix,
    const float* __restrict__ alpha, const float* __restrict__ beta,
    float* __restrict__ out)
{
    // B-fragment-ordered keys (tf32 bits): [kb][lane*2 + {0,1}]  (8 KB)
    __shared__ unsigned sB[NKB * 64];
    // Dim-pair planes for accumulation: [plane(4)][key]  f32x2  (8 KB)
    //   plane p of key j = (dim 2p, dim 2p+1); plane 3 = (dim6, 1.0)
    __shared__ u64 sK2[4 * CHUNK];

    const int bh   = blockIdx.y;
    const int h    = bh & (N_HEAD - 1);
    const int b    = bh >> 4;
    const int qb   = blockIdx.x;
    const int tid  = threadIdx.x;
    const int w    = tid >> 5;
    const int lane = tid & 31;
    const int gq   = lane >> 2;       // row group 0..7
    const int tc   = lane & 3;        // thread-in-group 0..3
    const float* obase = o + (size_t)b * N_TOK * DMODEL + h * 8;

    // w_k = sigmoid(m0-m1); fold w_k * log2e / sqrt(7) into Q.
    float m0 = mix[2 * h], m1 = mix[2 * h + 1];
    float wk = 1.0f / (1.0f + __expf(m1 - m0));
    const float coef = wk * 1.4426950408889634f * 0.3779644730092272f;

    // --- Q A-fragment (m16n8k8.tf32 row-major): rows r0=gq, r1=gq+8;
    //     a0:(r0,tc) a1:(r1,tc) a2:(r0,tc+4) a3:(r1,tc+4); col 7 = pad 0.
    const int r0 = qb * QT + w * 16 + gq;
    const int r1 = r0 + 8;
    float qa0 = obase[(size_t)r0 * DMODEL + 1 + tc];
    float qa1 = obase[(size_t)r1 * DMODEL + 1 + tc];
    float qa2 = (tc == 3) ? 0.0f : obase[(size_t)r0 * DMODEL + 1 + tc + 4];
    float qa3 = (tc == 3) ? 0.0f : obase[(size_t)r1 * DMODEL + 1 + tc + 4];
    unsigned a0 = tf32cvt(qa0 * coef);
    unsigned a1 = tf32cvt(qa1 * coef);
    unsigned a2 = tf32cvt(qa2 * coef);
    unsigned a3 = tf32cvt(qa3 * coef);

    // Accumulators: rows r0 / r1, 4 f32x2 planes each (plane3.hi = denom l).
    u64 yA0 = 0, yA1 = 0, yA2 = 0, yA3 = 0;
    u64 yB0 = 0, yB1 = 0, yB2 = 0, yB3 = 0;

    for (int ck = 0; ck < NCHUNK; ck++) {
        // ---- Load chunk: thread j handles key j of the chunk.
        {
            const int j  = tid;
            const int jg = ck * CHUNK + j;
            const float* kr = obase + (size_t)jg * DMODEL;
            float4 v0 = *(const float4*)kr;        // real, d0, d1, d2
            float4 v1 = *(const float4*)(kr + 4);  // d3, d4, d5, d6
            float d0 = v0.y, d1 = v0.z, d2 = v0.w, d3 = v1.x;
            float d4 = v1.y, d5 = v1.z, d6 = v1.w;
            // B fragment (col-major 8x8): b0 = K[key kb*8+gq][dim tc],
            // b1 = [dim tc+4]. Store so lane reads sB[kb*64 + lane*2 +{0,1}]:
            // key pos=j&7 occupies lanes 4*pos..4*pos+3: [pos*8+2c]=dim c,
            // [pos*8+2c+1]=dim c+4 (c=3 -> dim7 = 0, killed by Q pad anyway).
            int kb = j >> 3, pos = j & 7;
            uint4* dst = (uint4*)(sB + kb * 64 + pos * 8);
            dst[0] = make_uint4(tf32cvt(d0), tf32cvt(d4), tf32cvt(d1), tf32cvt(d5));
            dst[1] = make_uint4(tf32cvt(d2), tf32cvt(d6), tf32cvt(d3), 0u);
            // Accumulation planes (full fp32).
            sK2[0 * CHUNK + j] = f2pack(d0, d1);
            sK2[1 * CHUNK + j] = f2pack(d2, d3);
            sK2[2 * CHUNK + j] = f2pack(d4, d5);
            sK2[3 * CHUNK + j] = f2pack(d6, 1.0f);
        }
        __syncthreads();

        #pragma unroll 4
        for (int kb = 0; kb < NKB; kb++) {
            // B fragment for keys kb*8..kb*8+7.
            const unsigned* bp = sB + kb * 64 + lane * 2;
            unsigned b0 = bp[0], b1 = bp[1];
            float d0, d1, d2, d3;
            asm("mma.sync.aligned.m16n8k8.row.col.f32.tf32.tf32.f32 "
                "{%0,%1,%2,%3},{%4,%5,%6,%7},{%8,%9},{%10,%11,%12,%13};"
                : "=f"(d0), "=f"(d1), "=f"(d2), "=f"(d3)
                : "r"(a0), "r"(a1), "r"(a2), "r"(a3), "r"(b0), "r"(b1),
                  "f"(0.0f), "f"(0.0f), "f"(0.0f), "f"(0.0f));
            // C layout: d0=(r0, key jj) d1=(r0, jj+1) d2=(r1, jj) d3=(r1, jj+1)
            // where jj = kb*8 + 2*tc. Logits are pre-scaled -> direct ex2.
            float e0 = fast_ex2(d0), e1 = fast_ex2(d1);
            float e2 = fast_ex2(d2), e3 = fast_ex2(d3);
            const int jj = kb * 8 + 2 * tc;           // even -> 16B aligned
            u64 K0a = sK2[0 * CHUNK + jj], K0b = sK2[0 * CHUNK + jj + 1];
            u64 K1a = sK2[1 * CHUNK + jj], K1b = sK2[1 * CHUNK + jj + 1];
            u64 K2a = sK2[2 * CHUNK + jj], K2b = sK2[2 * CHUNK + jj + 1];
            u64 K3a = sK2[3 * CHUNK + jj], K3b = sK2[3 * CHUNK + jj + 1];
            u64 e00 = f2pack(e0, e0), e01 = f2pack(e1, e1);
            u64 e10 = f2pack(e2, e2), e11 = f2pack(e3, e3);
            yA0 = f2fma(K0a, e00, yA0);  yA0 = f2fma(K0b, e01, yA0);
            yA1 = f2fma(K1a, e00, yA1);  yA1 = f2fma(K1b, e01, yA1);
            yA2 = f2fma(K2a, e00, yA2);  yA2 = f2fma(K2b, e01, yA2);
            yA3 = f2fma(K3a, e00, yA3);  yA3 = f2fma(K3b, e01, yA3);
            yB0 = f2fma(K0a, e10, yB0);  yB0 = f2fma(K0b, e11, yB0);
            yB1 = f2fma(K1a, e10, yB1);  yB1 = f2fma(K1b, e11, yB1);
            yB2 = f2fma(K2a, e10, yB2);  yB2 = f2fma(K2b, e11, yB2);
            yB3 = f2fma(K3a, e10, yB3);  yB3 = f2fma(K3b, e11, yB3);
        }
        __syncthreads();
    }

    // ---- Quad reduction: threads tc=0..3 hold disjoint key subsets.
    const unsigned FULL = 0xffffffffu;
    #pragma unroll
    for (int m = 1; m < 4; m <<= 1) {
        yA0 = f2add(yA0, __shfl_xor_sync(FULL, yA0, m));
        yA1 = f2add(yA1, __shfl_xor_sync(FULL, yA1, m));
        yA2 = f2add(yA2, __shfl_xor_sync(FULL, yA2, m));
        yA3 = f2add(yA3, __shfl_xor_sync(FULL, yA3, m));
        yB0 = f2add(yB0, __shfl_xor_sync(FULL, yB0, m));
        yB1 = f2add(yB1, __shfl_xor_sync(FULL, yB1, m));
        yB2 = f2add(yB2, __shfl_xor_sync(FULL, yB2, m));
        yB3 = f2add(yB3, __shfl_xor_sync(FULL, yB3, m));
    }

    if (tc != 0) return;

    float av = 1.0f / (1.0f + __expf(-alpha[h]));
    float bv = tanhf(beta[h]);

    // Epilogue for rows r0 (yA*) and r1 (yB*).
    #pragma unroll
    for (int half = 0; half < 2; half++) {
        const int n = half ? r1 : r0;
        u64 p0 = half ? yB0 : yA0, p1 = half ? yB1 : yA1;
        u64 p2 = half ? yB2 : yA2, p3 = half ? yB3 : yA3;
        float y[7], l;
        f2unpack(p0, y[0], y[1]);
        f2unpack(p1, y[2], y[3]);
        f2unpack(p2, y[4], y[5]);
        f2unpack(p3, y[6], l);
        float rinv = 1.0f / l;
        #pragma unroll
        for (int i = 0; i < 7; i++) y[i] *= rinv;

        float4 q0 = *(const float4*)(obase + (size_t)n * DMODEL);
        float4 q1 = *(const float4*)(obase + (size_t)n * DMODEL + 4);
        float real = q0.x;
        float qo[7] = {q0.y, q0.z, q0.w, q1.x, q1.y, q1.z, q1.w};

        // Octonion cross product c = qo x y.
        float c[7];
        #pragma unroll
        for (int i = 0; i < 7; i++) c[i] = 0.0f;
        const int FI[7] = {0, 0, 0, 1, 1, 2, 2};
        const int FJ[7] = {1, 3, 6, 3, 4, 3, 5};
        const int FK[7] = {2, 4, 5, 5, 6, 6, 4};
        #pragma unroll
        for (int t = 0; t < 7; t++) {
            int i = FI[t], j = FJ[t], k = FK[t];
            c[k] += qo[i] * y[j] - qo[j] * y[i];
            c[i] += qo[j] * y[k] - qo[k] * y[j];
            c[j] += qo[k] * y[i] - qo[i] * y[k];
        }

        float im[7];
        float ns = real * real;
        #pragma unroll
        for (int i = 0; i < 7; i++) {
            im[i] = av * y[i] + bv * c[i];
            ns += im[i] * im[i];
        }
        float inv = 1.0f / fmaxf(sqrtf(ns), 1e-12f);

        float* op = out + ((size_t)(b * N_TOK + n)) * DMODEL + h * 8;
        *(float4*)(op)     = make_float4(real * inv, im[0] * inv, im[1] * inv, im[2] * inv);
        *(float4*)(op + 4) = make_float4(im[3] * inv, im[4] * inv, im[5] * inv, im[6] * inv);
    }
}

extern "C" void kernel_launch(void* const* d_in, const int* in_sizes, int n_in,
                              void* d_out, int out_size) {
    const float* o     = (const float*)d_in[0];
    const float* mix   = (const float*)d_in[1];
    const float* alpha = (const float*)d_in[2];
    const float* beta  = (const float*)d_in[3];
    float* out = (float*)d_out;
    (void)in_sizes; (void)n_in; (void)out_size;

    dim3 grid(N_TOK / QT, N_BATCH * N_HEAD);   // (16, 32) = 512 CTAs, one wave
    g2_attn_tc<<<grid, TPB>>>(o, mix, alpha, beta, out);
}

// round 15
// speedup vs baseline: 1.1739x; 1.1497x over previous
#include <cuda_runtime.h>

// G2InvariantAttention — GB300 sm_103a — Round 15: BOTH GEMMs on tensor pipe.
//   mma1: S[16q x 8k] = Q·K^T (tf32, as R14 — proven layout).
//   mma2: y[16q x 8dims] += E·K2 where E = ex2(S) (A-frag built from mma1's
//         C-frag via 8 shfl + 4 sel), K2[key][dim] with dim7 = 1.0 so the
//         softmax denominator appears as output column 7. E's tf32 rounding
//         cancels in y/l (shared weights); only K2's tf32 error remains.
//   Removes the 8x LDS.64 + 16 FMA2 SIMT accumulation (L1 was 76% -> wall).
//   Two mma2 accumulator sets (even/odd kb) break the accumulate chain.
// Exact math: oct_cross(k,k)=0, v==k, scale wk*log2e/sqrt(7) folded into Q,
// no max-subtraction (logits bounded).

#define N_TOK   2048
#define N_HEAD  16
#define N_BATCH 2
#define DMODEL  128
#define TPB     256
#define CHUNK   256
#define NKB     (CHUNK / 8)          // 32 mma steps per chunk
#define NCHUNK  (N_TOK / CHUNK)      // 8
#define QT      128                  // queries per CTA

__device__ __forceinline__ float fast_ex2(float x) {
    float r; asm("ex2.approx.f32 %0,%1;" : "=f"(r) : "f"(x)); return r;
}
__device__ __forceinline__ unsigned tf32cvt(float x) {
    unsigned r; asm("cvt.rna.tf32.f32 %0,%1;" : "=r"(r) : "f"(x)); return r;
}

__global__ void __launch_bounds__(TPB, 4) g2_attn_tc2(
    const float* __restrict__ o, const float* __restrict__ mix,
    const float* __restrict__ alpha, const float* __restrict__ beta,
    float* __restrict__ out)
{
    // Score B frags:  b0 = K[key gq][dim tc],  b1 = K[key gq][dim tc+4]
    __shared__ unsigned sBf[NKB * 64];   // 8 KB
    // Accum B frags:  b0 = K2[key tc][dim gq], b1 = K2[key tc+4][dim gq]
    __shared__ unsigned sBa[NKB * 64];   // 8 KB

    const int bh   = blockIdx.y;
    const int h    = bh & (N_HEAD - 1);
    const int b    = bh >> 4;
    const int qb   = blockIdx.x;
    const int tid  = threadIdx.x;
    const int w    = tid >> 5;
    const int lane = tid & 31;
    const int gq   = lane >> 2;
    const int tc   = lane & 3;
    const unsigned FULL = 0xffffffffu;
    const float* obase = o + (size_t)b * N_TOK * DMODEL + h * 8;

    float m0 = mix[2 * h], m1 = mix[2 * h + 1];
    float wk = 1.0f / (1.0f + __expf(m1 - m0));
    const float coef = wk * 1.4426950408889634f * 0.3779644730092272f;

    // Q A-fragment (row-major m16k8): rows r0=..gq, r1=r0+8; col 7 = 0 pad.
    const int r0 = qb * QT + w * 16 + gq;
    const int r1 = r0 + 8;
    float qa0 = obase[(size_t)r0 * DMODEL + 1 + tc];
    float qa1 = obase[(size_t)r1 * DMODEL + 1 + tc];
    float qa2 = (tc == 3) ? 0.0f : obase[(size_t)r0 * DMODEL + 1 + tc + 4];
    float qa3 = (tc == 3) ? 0.0f : obase[(size_t)r1 * DMODEL + 1 + tc + 4];
    unsigned a0 = tf32cvt(qa0 * coef);
    unsigned a1 = tf32cvt(qa1 * coef);
    unsigned a2 = tf32cvt(qa2 * coef);
    unsigned a3 = tf32cvt(qa3 * coef);

    // y accumulators (C-frag layout: lane holds dims 2tc,2tc+1 for r0,r1).
    // Two sets (even/odd kb) to break the mma accumulate dependency chain.
    float yE0 = 0, yE1 = 0, yE2 = 0, yE3 = 0;
    float yO0 = 0, yO1 = 0, yO2 = 0, yO3 = 0;

    for (int ck = 0; ck < NCHUNK; ck++) {
        // ---- Load chunk: thread j handles key j.
        {
            const int j  = tid;
            const int jg = ck * CHUNK + j;
            const float* kr = obase + (size_t)jg * DMODEL;
            float4 v0 = *(const float4*)kr;        // real, d0, d1, d2
            float4 v1 = *(const float4*)(kr + 4);  // d3, d4, d5, d6
            float d[8] = {v0.y, v0.z, v0.w, v1.x, v1.y, v1.z, v1.w, 1.0f};
            int kb = j >> 3, pos = j & 7;
            // Score frag (R14-proven): [pos*8+2c]=dim c, [pos*8+2c+1]=dim c+4.
            uint4* dst = (uint4*)(sBf + kb * 64 + pos * 8);
            dst[0] = make_uint4(tf32cvt(d[0]), tf32cvt(d[4]), tf32cvt(d[1]), tf32cvt(d[5]));
            dst[1] = make_uint4(tf32cvt(d[2]), tf32cvt(d[6]), tf32cvt(d[3]), 0u);
            // Accum frag: word dim*8 + (pos<4 ? pos*2 : (pos-4)*2+1).
            unsigned* ab = sBa + kb * 64 + ((pos < 4) ? pos * 2 : (pos - 4) * 2 + 1);
            #pragma unroll
            for (int dd = 0; dd < 8; dd++) ab[dd * 8] = tf32cvt(d[dd]);
        }
        __syncthreads();

        #pragma unroll 4
        for (int kb = 0; kb < NKB; kb++) {
            const unsigned* bp = sBf + kb * 64 + lane * 2;
            unsigned b0 = bp[0], b1 = bp[1];
            float s0, s1, s2, s3;
            asm("mma.sync.aligned.m16n8k8.row.col.f32.tf32.tf32.f32 "
                "{%0,%1,%2,%3},{%4,%5,%6,%7},{%8,%9},{%10,%11,%12,%13};"
                : "=f"(s0), "=f"(s1), "=f"(s2), "=f"(s3)
                : "r"(a0), "r"(a1), "r"(a2), "r"(a3), "r"(b0), "r"(b1),
                  "f"(0.0f), "f"(0.0f), "f"(0.0f), "f"(0.0f));
            // C layout: s0=(r0,2tc) s1=(r0,2tc+1) s2=(r1,2tc) s3=(r1,2tc+1).
            float e0 = fast_ex2(s0), e1 = fast_ex2(s1);
            float e2 = fast_ex2(s2), e3 = fast_ex2(s3);

            // Build E A-fragment: need E[r0][tc], E[r1][tc], E[r0][tc+4], E[r1][tc+4].
            // Key m is held by lane tc' = m>>1 (same gq), component m&1.
            int srcA = (lane & ~3) | (tc >> 1);   // holds keys tc (comp tc&1)
            int srcB = srcA + 2;                  // holds keys tc+4
            float f0 = __shfl_sync(FULL, e0, srcA);
            float f1 = __shfl_sync(FULL, e1, srcA);
            float g0 = __shfl_sync(FULL, e2, srcA);
            float g1 = __shfl_sync(FULL, e3, srcA);
            float h0 = __shfl_sync(FULL, e0, srcB);
            float h1 = __shfl_sync(FULL, e1, srcB);
            float i0 = __shfl_sync(FULL, e2, srcB);
            float i1 = __shfl_sync(FULL, e3, srcB);
            bool odd = tc & 1;
            unsigned A0 = tf32cvt(odd ? f1 : f0);   // E[r0][tc]
            unsigned A1 = tf32cvt(odd ? g1 : g0);   // E[r1][tc]
            unsigned A2 = tf32cvt(odd ? h1 : h0);   // E[r0][tc+4]
            unsigned A3 = tf32cvt(odd ? i1 : i0);   // E[r1][tc+4]

            const unsigned* ap = sBa + kb * 64 + lane * 2;
            unsigned k0 = ap[0], k1 = ap[1];
            if (kb & 1) {
                asm("mma.sync.aligned.m16n8k8.row.col.f32.tf32.tf32.f32 "
                    "{%0,%1,%2,%3},{%4,%5,%6,%7},{%8,%9},{%0,%1,%2,%3};"
                    : "+f"(yO0), "+f"(yO1), "+f"(yO2), "+f"(yO3)
                    : "r"(A0), "r"(A1), "r"(A2), "r"(A3), "r"(k0), "r"(k1));
            } else {
                asm("mma.sync.aligned.m16n8k8.row.col.f32.tf32.tf32.f32 "
                    "{%0,%1,%2,%3},{%4,%5,%6,%7},{%8,%9},{%0,%1,%2,%3};"
                    : "+f"(yE0), "+f"(yE1), "+f"(yE2), "+f"(yE3)
                    : "r"(A0), "r"(A1), "r"(A2), "r"(A3), "r"(k0), "r"(k1));
            }
        }
        __syncthreads();
    }

    float yc0 = yE0 + yO0, yc1 = yE1 + yO1;
    float yc2 = yE2 + yO2, yc3 = yE3 + yO3;

    // Gather: lane tc holds dims {2tc, 2tc+1}; collect 8 dims on tc==0.
    float p0a = __shfl_down_sync(FULL, yc0, 1), p0b = __shfl_down_sync(FULL, yc1, 1);
    float p1a = __shfl_down_sync(FULL, yc0, 2), p1b = __shfl_down_sync(FULL, yc1, 2);
    float p2a = __shfl_down_sync(FULL, yc0, 3), p2b = __shfl_down_sync(FULL, yc1, 3);
    float q0a = __shfl_down_sync(FULL, yc2, 1), q0b = __shfl_down_sync(FULL, yc3, 1);
    float q1a = __shfl_down_sync(FULL, yc2, 2), q1b = __shfl_down_sync(FULL, yc3, 2);
    float q2a = __shfl_down_sync(FULL, yc2, 3), q2b = __shfl_down_sync(FULL, yc3, 3);

    if (tc != 0) return;

    float av = 1.0f / (1.0f + __expf(-alpha[h]));
    float bv = tanhf(beta[h]);

    float rowsY[2][8] = {
        {yc0, yc1, p0a, p0b, p1a, p1b, p2a, p2b},   // r0: dims 0..6, l
        {yc2, yc3, q0a, q0b, q1a, q1b, q2a, q2b}    // r1
    };

    #pragma unroll
    for (int half = 0; half < 2; half++) {
        const int n = half ? r1 : r0;
        float y[7], l = rowsY[half][7];
        #pragma unroll
        for (int i = 0; i < 7; i++) y[i] = rowsY[half][i];
        float rinv = 1.0f / l;
        #pragma unroll
        for (int i = 0; i < 7; i++) y[i] *= rinv;

        float4 q0 = *(const float4*)(obase + (size_t)n * DMODEL);
        float4 q1 = *(const float4*)(obase + (size_t)n * DMODEL + 4);
        float real = q0.x;
        float qo[7] = {q0.y, q0.z, q0.w, q1.x, q1.y, q1.z, q1.w};

        float c[7];
        #pragma unroll
        for (int i = 0; i < 7; i++) c[i] = 0.0f;
        const int FI[7] = {0, 0, 0, 1, 1, 2, 2};
        const int FJ[7] = {1, 3, 6, 3, 4, 3, 5};
        const int FK[7] = {2, 4, 5, 5, 6, 6, 4};
        #pragma unroll
        for (int t = 0; t < 7; t++) {
            int i = FI[t], j = FJ[t], k = FK[t];
            c[k] += qo[i] * y[j] - qo[j] * y[i];
            c[i] += qo[j] * y[k] - qo[k] * y[j];
            c[j] += qo[k] * y[i] - qo[i] * y[k];
        }

        float im[7];
        float ns = real * real;
        #pragma unroll
        for (int i = 0; i < 7; i++) {
            im[i] = av * y[i] + bv * c[i];
            ns += im[i] * im[i];
        }
        float inv = 1.0f / fmaxf(sqrtf(ns), 1e-12f);

        float* op = out + ((size_t)(b * N_TOK + n)) * DMODEL + h * 8;
        *(float4*)(op)     = make_float4(real * inv, im[0] * inv, im[1] * inv, im[2] * inv);
        *(float4*)(op + 4) = make_float4(im[3] * inv, im[4] * inv, im[5] * inv, im[6] * inv);
    }
}

extern "C" void kernel_launch(void* const* d_in, const int* in_sizes, int n_in,
                              void* d_out, int out_size) {
    const float* o     = (const float*)d_in[0];
    const float* mix   = (const float*)d_in[1];
    const float* alpha = (const float*)d_in[2];
    const float* beta  = (const float*)d_in[3];
    float* out = (float*)d_out;
    (void)in_sizes; (void)n_in; (void)out_size;

    dim3 grid(N_TOK / QT, N_BATCH * N_HEAD);   // (16, 32) = 512 CTAs, one wave
    g2_attn_tc2<<<grid, TPB>>>(o, mix, alpha, beta, out);
}

// round 16
// speedup vs baseline: 2.0205x; 1.7212x over previous
#include <cuda_runtime.h>

// G2InvariantAttention — GB300 sm_103a — Round 16: shuffle-free E fragment.
//   mma1 (scores) stores key p at COLUMN sigma(p) = (p<4 ? 2p : 2(p-4)+1), so
//   its C fragment lands exactly in mma2's A-fragment layout:
//     lane(gq,tc): s0=(r0,key tc) s1=(r0,key tc+4) s2=(r1,key tc) s3=(r1,tc+4)
//   -> A-frag = register renaming (A0=e(s0),A1=e(s2),A2=e(s1),A3=e(s3)).
//   Removes 8 SHFL + 4 SEL + 4 CVT per kb-step (12 of 27 issue slots; alu
//   pipe was 37%). E passed as raw f32 bits (tf32 truncation; error cancels
//   in y/l). sBa (K2) fragment unchanged — indexes actual keys.
// Exact math: oct_cross(k,k)=0, v==k, scale wk*log2e/sqrt(7) folded into Q,
// no max-subtraction (logits bounded), K2 dim7=1.0 -> denominator free.

#define N_TOK   2048
#define N_HEAD  16
#define N_BATCH 2
#define DMODEL  128
#define TPB     256
#define CHUNK   256
#define NKB     (CHUNK / 8)          // 32 mma steps per chunk
#define NCHUNK  (N_TOK / CHUNK)      // 8
#define QT      128                  // queries per CTA

__device__ __forceinline__ float fast_ex2(float x) {
    float r; asm("ex2.approx.f32 %0,%1;" : "=f"(r) : "f"(x)); return r;
}
__device__ __forceinline__ unsigned tf32cvt(float x) {
    unsigned r; asm("cvt.rna.tf32.f32 %0,%1;" : "=r"(r) : "f"(x)); return r;
}

__global__ void __launch_bounds__(TPB, 4) g2_attn_tc3(
    const float* __restrict__ o, const float* __restrict__ mix,
    const float* __restrict__ alpha, const float* __restrict__ beta,
    float* __restrict__ out)
{
    // Score B frags (keys column-PERMUTED): col 2t = key t, col 2t+1 = key t+4
    __shared__ unsigned sBf[NKB * 64];   // 8 KB
    // Accum B frags: b0 = K2[key tc][dim gq], b1 = K2[key tc+4][dim gq]
    __shared__ unsigned sBa[NKB * 64];   // 8 KB

    const int bh   = blockIdx.y;
    const int h    = bh & (N_HEAD - 1);
    const int b    = bh >> 4;
    const int qb   = blockIdx.x;
    const int tid  = threadIdx.x;
    const int w    = tid >> 5;
    const int lane = tid & 31;
    const int gq   = lane >> 2;
    const int tc   = lane & 3;
    const unsigned FULL = 0xffffffffu;
    const float* obase = o + (size_t)b * N_TOK * DMODEL + h * 8;

    float m0 = mix[2 * h], m1 = mix[2 * h + 1];
    float wk = 1.0f / (1.0f + __expf(m1 - m0));
    const float coef = wk * 1.4426950408889634f * 0.3779644730092272f;

    // Q A-fragment (row-major m16k8): rows r0, r1 = r0+8; col 7 = 0 pad.
    const int r0 = qb * QT + w * 16 + gq;
    const int r1 = r0 + 8;
    float qa0 = obase[(size_t)r0 * DMODEL + 1 + tc];
    float qa1 = obase[(size_t)r1 * DMODEL + 1 + tc];
    float qa2 = (tc == 3) ? 0.0f : obase[(size_t)r0 * DMODEL + 1 + tc + 4];
    float qa3 = (tc == 3) ? 0.0f : obase[(size_t)r1 * DMODEL + 1 + tc + 4];
    unsigned a0 = tf32cvt(qa0 * coef);
    unsigned a1 = tf32cvt(qa1 * coef);
    unsigned a2 = tf32cvt(qa2 * coef);
    unsigned a3 = tf32cvt(qa3 * coef);

    // y accumulators: lane holds dims {2tc, 2tc+1} for rows r0, r1.
    // Two sets (even/odd kb) break the mma accumulate dependency chain.
    float yE0 = 0, yE1 = 0, yE2 = 0, yE3 = 0;
    float yO0 = 0, yO1 = 0, yO2 = 0, yO3 = 0;

    for (int ck = 0; ck < NCHUNK; ck++) {
        // ---- Load chunk: thread j handles key j.
        {
            const int j  = tid;
            const int jg = ck * CHUNK + j;
            const float* kr = obase + (size_t)jg * DMODEL;
            float4 v0 = *(const float4*)kr;        // real, d0, d1, d2
            float4 v1 = *(const float4*)(kr + 4);  // d3, d4, d5, d6
            float d[8] = {v0.y, v0.z, v0.w, v1.x, v1.y, v1.z, v1.w, 1.0f};
            int kb = j >> 3, pos = j & 7;
            // PERMUTED column for the score frag: key pos -> column cpos.
            int cpos = (pos < 4) ? 2 * pos : 2 * (pos - 4) + 1;
            uint4* dst = (uint4*)(sBf + kb * 64 + cpos * 8);
            dst[0] = make_uint4(tf32cvt(d[0]), tf32cvt(d[4]), tf32cvt(d[1]), tf32cvt(d[5]));
            dst[1] = make_uint4(tf32cvt(d[2]), tf32cvt(d[6]), tf32cvt(d[3]), 0u);
            // Accum frag (actual key indexing — unchanged from R15).
            unsigned* ab = sBa + kb * 64 + ((pos < 4) ? pos * 2 : (pos - 4) * 2 + 1);
            #pragma unroll
            for (int dd = 0; dd < 8; dd++) ab[dd * 8] = tf32cvt(d[dd]);
        }
        __syncthreads();

        #pragma unroll 4
        for (int kb = 0; kb < NKB; kb++) {
            const unsigned* bp = sBf + kb * 64 + lane * 2;
            unsigned b0 = bp[0], b1 = bp[1];
            float s0, s1, s2, s3;
            asm("mma.sync.aligned.m16n8k8.row.col.f32.tf32.tf32.f32 "
                "{%0,%1,%2,%3},{%4,%5,%6,%7},{%8,%9},{%10,%11,%12,%13};"
                : "=f"(s0), "=f"(s1), "=f"(s2), "=f"(s3)
                : "r"(a0), "r"(a1), "r"(a2), "r"(a3), "r"(b0), "r"(b1),
                  "f"(0.0f), "f"(0.0f), "f"(0.0f), "f"(0.0f));
            // Permuted C: s0=(r0,key tc) s1=(r0,key tc+4)
            //             s2=(r1,key tc) s3=(r1,key tc+4)
            // -> E A-fragment by pure register renaming (raw f32 bits; HW
            //    truncates to tf32, error cancels in y/l).
            unsigned A0 = __float_as_uint(fast_ex2(s0));   // E[r0][tc]
            unsigned A1 = __float_as_uint(fast_ex2(s2));   // E[r1][tc]
            unsigned A2 = __float_as_uint(fast_ex2(s1));   // E[r0][tc+4]
            unsigned A3 = __float_as_uint(fast_ex2(s3));   // E[r1][tc+4]

            const unsigned* ap = sBa + kb * 64 + lane * 2;
            unsigned k0 = ap[0], k1 = ap[1];
            if (kb & 1) {
                asm("mma.sync.aligned.m16n8k8.row.col.f32.tf32.tf32.f32 "
                    "{%0,%1,%2,%3},{%4,%5,%6,%7},{%8,%9},{%0,%1,%2,%3};"
                    : "+f"(yO0), "+f"(yO1), "+f"(yO2), "+f"(yO3)
                    : "r"(A0), "r"(A1), "r"(A2), "r"(A3), "r"(k0), "r"(k1));
            } else {
                asm("mma.sync.aligned.m16n8k8.row.col.f32.tf32.tf32.f32 "
                    "{%0,%1,%2,%3},{%4,%5,%6,%7},{%8,%9},{%0,%1,%2,%3};"
                    : "+f"(yE0), "+f"(yE1), "+f"(yE2), "+f"(yE3)
                    : "r"(A0), "r"(A1), "r"(A2), "r"(A3), "r"(k0), "r"(k1));
            }
        }
        __syncthreads();
    }

    float yc0 = yE0 + yO0, yc1 = yE1 + yO1;
    float yc2 = yE2 + yO2, yc3 = yE3 + yO3;

    // Gather: lane tc holds dims {2tc, 2tc+1}; collect 8 dims on tc==0.
    float p0a = __shfl_down_sync(FULL, yc0, 1), p0b = __shfl_down_sync(FULL, yc1, 1);
    float p1a = __shfl_down_sync(FULL, yc0, 2), p1b = __shfl_down_sync(FULL, yc1, 2);
    float p2a = __shfl_down_sync(FULL, yc0, 3), p2b = __shfl_down_sync(FULL, yc1, 3);
    float q0a = __shfl_down_sync(FULL, yc2, 1), q0b = __shfl_down_sync(FULL, yc3, 1);
    float q1a = __shfl_down_sync(FULL, yc2, 2), q1b = __shfl_down_sync(FULL, yc3, 2);
    float q2a = __shfl_down_sync(FULL, yc2, 3), q2b = __shfl_down_sync(FULL, yc3, 3);

    if (tc != 0) return;

    float av = 1.0f / (1.0f + __expf(-alpha[h]));
    float bv = tanhf(beta[h]);

    float rowsY[2][8] = {
        {yc0, yc1, p0a, p0b, p1a, p1b, p2a, p2b},   // r0: dims 0..6, l
        {yc2, yc3, q0a, q0b, q1a, q1b, q2a, q2b}    // r1
    };

    #pragma unroll
    for (int half = 0; half < 2; half++) {
        const int n = half ? r1 : r0;
        float y[7], l = rowsY[half][7];
        #pragma unroll
        for (int i = 0; i < 7; i++) y[i] = rowsY[half][i];
        float rinv = 1.0f / l;
        #pragma unroll
        for (int i = 0; i < 7; i++) y[i] *= rinv;

        float4 q0 = *(const float4*)(obase + (size_t)n * DMODEL);
        float4 q1 = *(const float4*)(obase + (size_t)n * DMODEL + 4);
        float real = q0.x;
        float qo[7] = {q0.y, q0.z, q0.w, q1.x, q1.y, q1.z, q1.w};

        float c[7];
        #pragma unroll
        for (int i = 0; i < 7; i++) c[i] = 0.0f;
        const int FI[7] = {0, 0, 0, 1, 1, 2, 2};
        const int FJ[7] = {1, 3, 6, 3, 4, 3, 5};
        const int FK[7] = {2, 4, 5, 5, 6, 6, 4};
        #pragma unroll
        for (int t = 0; t < 7; t++) {
            int i = FI[t], j = FJ[t], k = FK[t];
            c[k] += qo[i] * y[j] - qo[j] * y[i];
            c[i] += qo[j] * y[k] - qo[k] * y[j];
            c[j] += qo[k] * y[i] - qo[i] * y[k];
        }

        float im[7];
        float ns = real * real;
        #pragma unroll
        for (int i = 0; i < 7; i++) {
            im[i] = av * y[i] + bv * c[i];
            ns += im[i] * im[i];
        }
        float inv = 1.0f / fmaxf(sqrtf(ns), 1e-12f);

        float* op = out + ((size_t)(b * N_TOK + n)) * DMODEL + h * 8;
        *(float4*)(op)     = make_float4(real * inv, im[0] * inv, im[1] * inv, im[2] * inv);
        *(float4*)(op + 4) = make_float4(im[3] * inv, im[4] * inv, im[5] * inv, im[6] * inv);
    }
}

extern "C" void kernel_launch(void* const* d_in, const int* in_sizes, int n_in,
                              void* d_out, int out_size) {
    const float* o     = (const float*)d_in[0];
    const float* mix   = (const float*)d_in[1];
    const float* alpha = (const float*)d_in[2];
    const float* beta  = (const float*)d_in[3];
    float* out = (float*)d_out;
    (void)in_sizes; (void)n_in; (void)out_size;

    dim3 grid(N_TOK / QT, N_BATCH * N_HEAD);   // (16, 32) = 512 CTAs, one wave
    g2_attn_tc3<<<grid, TPB>>>(o, mix, alpha, beta, out);
}

// round 17
// speedup vs baseline: 2.3176x; 1.1471x over previous
#include <cuda_runtime.h>

// G2InvariantAttention — GB300 sm_103a — Round 17: 32 queries per warp.
//   K fragments (score b0,b1 + accum k0,k1) are query-independent: process
//   TWO m16 A-fragments per warp (rows w*32+{gq,+8,+16,+24}) so each LDS
//   feeds 256 q*k (was 128). Per-qk issue cost -23%, smem traffic -50%.
//   TPB=128 (4 warps x 32q = 128q/CTA), same 512-CTA grid, regs capped via
//   launch_bounds(128,6). Four accumulator groups (A/B x even/odd kb) keep
//   the mma dependency chains broken.
//   Fragment layouts byte-identical to the R16-verified ones (column
//   permutation sigma(p) = p<4 ? 2p : 2(p-4)+1 makes mma1's C fragment land
//   directly in mma2's A layout — no shuffles).
// Exact math: oct_cross(k,k)=0, v==k, scale wk*log2e/sqrt(7) folded into Q,
// no max-subtraction (logits bounded), K2 dim7=1.0 -> denominator free.

#define N_TOK   2048
#define N_HEAD  16
#define N_BATCH 2
#define DMODEL  128
#define TPB     128
#define CHUNK   256
#define NKB     (CHUNK / 8)          // 32 mma steps per chunk
#define NCHUNK  (N_TOK / CHUNK)      // 8
#define QT      128                  // queries per CTA (4 warps x 32)

__device__ __forceinline__ float fast_ex2(float x) {
    float r; asm("ex2.approx.f32 %0,%1;" : "=f"(r) : "f"(x)); return r;
}
__device__ __forceinline__ unsigned tf32cvt(float x) {
    unsigned r; asm("cvt.rna.tf32.f32 %0,%1;" : "=r"(r) : "f"(x)); return r;
}

__global__ void __launch_bounds__(TPB, 6) g2_attn_tc4(
    const float* __restrict__ o, const float* __restrict__ mix,
    const float* __restrict__ alpha, const float* __restrict__ beta,
    float* __restrict__ out)
{
    // Score B frags (keys column-permuted; R16-verified layout).
    __shared__ unsigned sBf[NKB * 64];   // 8 KB
    // Accum B frags (R15/R16-verified layout).
    __shared__ unsigned sBa[NKB * 64];   // 8 KB

    const int bh   = blockIdx.y;
    const int h    = bh & (N_HEAD - 1);
    const int b    = bh >> 4;
    const int qb   = blockIdx.x;
    const int tid  = threadIdx.x;
    const int w    = tid >> 5;           // 0..3
    const int lane = tid & 31;
    const int gq   = lane >> 2;
    const int tc   = lane & 3;
    const unsigned FULL = 0xffffffffu;
    const float* obase = o + (size_t)b * N_TOK * DMODEL + h * 8;

    float m0 = mix[2 * h], m1 = mix[2 * h + 1];
    float wk = 1.0f / (1.0f + __expf(m1 - m0));
    const float coef = wk * 1.4426950408889634f * 0.3779644730092272f;

    // Two Q A-fragments: group A rows (r0, r1), group B rows (r2, r3).
    const int r0 = qb * QT + w * 32 + gq;
    const int r1 = r0 + 8;
    const int r2 = r0 + 16;
    const int r3 = r0 + 24;

    unsigned a0, a1, a2, a3, c0, c1, c2, c3;
    {
        float v;
        v = obase[(size_t)r0 * DMODEL + 1 + tc];                      a0 = tf32cvt(v * coef);
        v = obase[(size_t)r1 * DMODEL + 1 + tc];                      a1 = tf32cvt(v * coef);
        v = (tc == 3) ? 0.0f : obase[(size_t)r0 * DMODEL + 5 + tc];   a2 = tf32cvt(v * coef);
        v = (tc == 3) ? 0.0f : obase[(size_t)r1 * DMODEL + 5 + tc];   a3 = tf32cvt(v * coef);
        v = obase[(size_t)r2 * DMODEL + 1 + tc];                      c0 = tf32cvt(v * coef);
        v = obase[(size_t)r3 * DMODEL + 1 + tc];                      c1 = tf32cvt(v * coef);
        v = (tc == 3) ? 0.0f : obase[(size_t)r2 * DMODEL + 5 + tc];   c2 = tf32cvt(v * coef);
        v = (tc == 3) ? 0.0f : obase[(size_t)r3 * DMODEL + 5 + tc];   c3 = tf32cvt(v * coef);
    }

    // y accumulators: lane holds dims {2tc,2tc+1}; 4 groups (A/B x even/odd).
    float yAE0 = 0, yAE1 = 0, yAE2 = 0, yAE3 = 0;
    float yAO0 = 0, yAO1 = 0, yAO2 = 0, yAO3 = 0;
    float yBE0 = 0, yBE1 = 0, yBE2 = 0, yBE3 = 0;
    float yBO0 = 0, yBO1 = 0, yBO2 = 0, yBO3 = 0;

    for (int ck = 0; ck < NCHUNK; ck++) {
        // ---- Load chunk: 128 threads x 2 keys.
        #pragma unroll
        for (int rep = 0; rep < CHUNK / TPB; rep++) {
            const int j  = rep * TPB + tid;
            const int jg = ck * CHUNK + j;
            const float* kr = obase + (size_t)jg * DMODEL;
            float4 v0 = *(const float4*)kr;        // real, d0, d1, d2
            float4 v1 = *(const float4*)(kr + 4);  // d3, d4, d5, d6
            float d[8] = {v0.y, v0.z, v0.w, v1.x, v1.y, v1.z, v1.w, 1.0f};
            int kb = j >> 3, pos = j & 7;
            int cpos = (pos < 4) ? 2 * pos : 2 * (pos - 4) + 1;
            uint4* dst = (uint4*)(sBf + kb * 64 + cpos * 8);
            dst[0] = make_uint4(tf32cvt(d[0]), tf32cvt(d[4]), tf32cvt(d[1]), tf32cvt(d[5]));
            dst[1] = make_uint4(tf32cvt(d[2]), tf32cvt(d[6]), tf32cvt(d[3]), 0u);
            unsigned* ab = sBa + kb * 64 + ((pos < 4) ? pos * 2 : (pos - 4) * 2 + 1);
            #pragma unroll
            for (int dd = 0; dd < 8; dd++) ab[dd * 8] = tf32cvt(d[dd]);
        }
        __syncthreads();

        #pragma unroll 4
        for (int kb = 0; kb < NKB; kb++) {
            const unsigned* bp = sBf + kb * 64 + lane * 2;
            unsigned b0 = bp[0], b1 = bp[1];
            const unsigned* ap = sBa + kb * 64 + lane * 2;
            unsigned k0 = ap[0], k1 = ap[1];

            // Scores for both query groups (shared B fragment).
            float s0, s1, s2, s3, t0, t1, t2, t3;
            asm("mma.sync.aligned.m16n8k8.row.col.f32.tf32.tf32.f32 "
                "{%0,%1,%2,%3},{%4,%5,%6,%7},{%8,%9},{%10,%11,%12,%13};"
                : "=f"(s0), "=f"(s1), "=f"(s2), "=f"(s3)
                : "r"(a0), "r"(a1), "r"(a2), "r"(a3), "r"(b0), "r"(b1),
                  "f"(0.0f), "f"(0.0f), "f"(0.0f), "f"(0.0f));
            asm("mma.sync.aligned.m16n8k8.row.col.f32.tf32.tf32.f32 "
                "{%0,%1,%2,%3},{%4,%5,%6,%7},{%8,%9},{%10,%11,%12,%13};"
                : "=f"(t0), "=f"(t1), "=f"(t2), "=f"(t3)
                : "r"(c0), "r"(c1), "r"(c2), "r"(c3), "r"(b0), "r"(b1),
                  "f"(0.0f), "f"(0.0f), "f"(0.0f), "f"(0.0f));

            // Permuted C -> E A-fragments by register renaming (raw f32 bits).
            unsigned EA0 = __float_as_uint(fast_ex2(s0));
            unsigned EA1 = __float_as_uint(fast_ex2(s2));
            unsigned EA2 = __float_as_uint(fast_ex2(s1));
            unsigned EA3 = __float_as_uint(fast_ex2(s3));
            unsigned EB0 = __float_as_uint(fast_ex2(t0));
            unsigned EB1 = __float_as_uint(fast_ex2(t2));
            unsigned EB2 = __float_as_uint(fast_ex2(t1));
            unsigned EB3 = __float_as_uint(fast_ex2(t3));

            if (kb & 1) {
                asm("mma.sync.aligned.m16n8k8.row.col.f32.tf32.tf32.f32 "
                    "{%0,%1,%2,%3},{%4,%5,%6,%7},{%8,%9},{%0,%1,%2,%3};"
                    : "+f"(yAO0), "+f"(yAO1), "+f"(yAO2), "+f"(yAO3)
                    : "r"(EA0), "r"(EA1), "r"(EA2), "r"(EA3), "r"(k0), "r"(k1));
                asm("mma.sync.aligned.m16n8k8.row.col.f32.tf32.tf32.f32 "
                    "{%0,%1,%2,%3},{%4,%5,%6,%7},{%8,%9},{%0,%1,%2,%3};"
                    : "+f"(yBO0), "+f"(yBO1), "+f"(yBO2), "+f"(yBO3)
                    : "r"(EB0), "r"(EB1), "r"(EB2), "r"(EB3), "r"(k0), "r"(k1));
            } else {
                asm("mma.sync.aligned.m16n8k8.row.col.f32.tf32.tf32.f32 "
                    "{%0,%1,%2,%3},{%4,%5,%6,%7},{%8,%9},{%0,%1,%2,%3};"
                    : "+f"(yAE0), "+f"(yAE1), "+f"(yAE2), "+f"(yAE3)
                    : "r"(EA0), "r"(EA1), "r"(EA2), "r"(EA3), "r"(k0), "r"(k1));
                asm("mma.sync.aligned.m16n8k8.row.col.f32.tf32.tf32.f32 "
                    "{%0,%1,%2,%3},{%4,%5,%6,%7},{%8,%9},{%0,%1,%2,%3};"
                    : "+f"(yBE0), "+f"(yBE1), "+f"(yBE2), "+f"(yBE3)
                    : "r"(EB0), "r"(EB1), "r"(EB2), "r"(EB3), "r"(k0), "r"(k1));
            }
        }
        __syncthreads();
    }

    float A0 = yAE0 + yAO0, A1 = yAE1 + yAO1, A2 = yAE2 + yAO2, A3 = yAE3 + yAO3;
    float B0 = yBE0 + yBO0, B1 = yBE1 + yBO1, B2 = yBE2 + yBO2, B3 = yBE3 + yBO3;

    // Gather dims: lane tc holds dims {2tc,2tc+1} -> collect 8 on tc==0.
    float rows[4][8];
    #pragma unroll
    for (int g = 0; g < 2; g++) {
        float u0 = g ? B0 : A0, u1 = g ? B1 : A1;   // row rX (lower of pair)
        float u2 = g ? B2 : A2, u3 = g ? B3 : A3;   // row rX+8
        rows[2 * g + 0][0] = u0;  rows[2 * g + 0][1] = u1;
        rows[2 * g + 1][0] = u2;  rows[2 * g + 1][1] = u3;
        #pragma unroll
        for (int s = 1; s < 4; s++) {
            rows[2 * g + 0][2 * s]     = __shfl_down_sync(FULL, u0, s);
            rows[2 * g + 0][2 * s + 1] = __shfl_down_sync(FULL, u1, s);
            rows[2 * g + 1][2 * s]     = __shfl_down_sync(FULL, u2, s);
            rows[2 * g + 1][2 * s + 1] = __shfl_down_sync(FULL, u3, s);
        }
    }

    if (tc != 0) return;

    float av = 1.0f / (1.0f + __expf(-alpha[h]));
    float bv = tanhf(beta[h]);
    const int rowN[4] = {r0, r1, r2, r3};

    #pragma unroll
    for (int rr = 0; rr < 4; rr++) {
        const int n = rowN[rr];
        float y[7], l = rows[rr][7];
        #pragma unroll
        for (int i = 0; i < 7; i++) y[i] = rows[rr][i];
        float rinv = 1.0f / l;
        #pragma unroll
        for (int i = 0; i < 7; i++) y[i] *= rinv;

        float4 q0 = *(const float4*)(obase + (size_t)n * DMODEL);
        float4 q1 = *(const float4*)(obase + (size_t)n * DMODEL + 4);
        float real = q0.x;
        float qo[7] = {q0.y, q0.z, q0.w, q1.x, q1.y, q1.z, q1.w};

        float c[7];
        #pragma unroll
        for (int i = 0; i < 7; i++) c[i] = 0.0f;
        const int FI[7] = {0, 0, 0, 1, 1, 2, 2};
        const int FJ[7] = {1, 3, 6, 3, 4, 3, 5};
        const int FK[7] = {2, 4, 5, 5, 6, 6, 4};
        #pragma unroll
        for (int t = 0; t < 7; t++) {
            int i = FI[t], j = FJ[t], k = FK[t];
            c[k] += qo[i] * y[j] - qo[j] * y[i];
            c[i] += qo[j] * y[k] - qo[k] * y[j];
            c[j] += qo[k] * y[i] - qo[i] * y[k];
        }

        float im[7];
        float ns = real * real;
        #pragma unroll
        for (int i = 0; i < 7; i++) {
            im[i] = av * y[i] + bv * c[i];
            ns += im[i] * im[i];
        }
        float inv = 1.0f / fmaxf(sqrtf(ns), 1e-12f);

        float* op = out + ((size_t)(b * N_TOK + n)) * DMODEL + h * 8;
        *(float4*)(op)     = make_float4(real * inv, im[0] * inv, im[1] * inv, im[2] * inv);
        *(float4*)(op + 4) = make_float4(im[3] * inv, im[4] * inv, im[5] * inv, im[6] * inv);
    }
}

extern "C" void kernel_launch(void* const* d_in, const int* in_sizes, int n_in,
                              void* d_out, int out_size) {
    const float* o     = (const float*)d_in[0];
    const float* mix   = (const float*)d_in[1];
    const float* alpha = (const float*)d_in[2];
    const float* beta  = (const float*)d_in[3];
    float* out = (float*)d_out;
    (void)in_sizes; (void)n_in; (void)out_size;

    dim3 grid(N_TOK / QT, N_BATCH * N_HEAD);   // (16, 32) = 512 CTAs
    g2_attn_tc4<<<grid, TPB>>>(o, mix, alpha, beta, out);
}